// round 2
// baseline (speedup 1.0000x reference)
#include <cuda_runtime.h>
#include <cuda_bf16.h>

// Problem constants
#define BATCH 128
#define HEADS 12
#define NTOK  197            // 14*14 + 1
#define CDIM  768
#define HD    64
#define MROWS (BATCH * NTOK) // 25216 = 197 * 128  (divisible by 128!)
#define KDIM  768
#define N_QKV (3 * CDIM)     // 2304

// -------- scratch (static __device__ globals; no allocation allowed) --------
__device__ float g_q [BATCH * HEADS * NTOK * HD];
__device__ float g_k [BATCH * HEADS * NTOK * HD];
__device__ float g_v [BATCH * HEADS * NTOK * HD];
__device__ float g_rb[HEADS * NTOK * NTOK];
__device__ float g_ao[BATCH * NTOK * CDIM];

// ======================= rel-pos bias gather =======================
// rb[h][n][m] = table[idx[n*197+m]*12 + h]
__global__ void relbias_kernel(const float* __restrict__ table,
                               const int* __restrict__ idx) {
    int i = blockIdx.x * 256 + threadIdx.x;
    if (i < NTOK * NTOK) {
        int id = idx[i];
#pragma unroll
        for (int h = 0; h < HEADS; h++)
            g_rb[h * NTOK * NTOK + i] = table[id * HEADS + h];
    }
}

// ======================= SGEMM: QKV projection =======================
// C[m,n] = sum_k x[m,k] * qkv_w[n,k]  -> scatter into g_q/g_k/g_v with bias+scale
// Tiles: BM=128, BN=64, BK=16, 256 threads, each thread 8x4 outputs.
#define BM 128
#define BN 64
#define BK 16

__global__ __launch_bounds__(256)
void qkv_gemm_kernel(const float* __restrict__ A, const float* __restrict__ Bw,
                     const float* __restrict__ q_bias, const float* __restrict__ v_bias) {
    __shared__ float As[BK][BM + 4];  // [k][m], padded rows
    __shared__ float Bs[BK][BN + 4];  // [k][n], padded rows

    const int tid = threadIdx.x;
    const int tx = tid & 15, ty = tid >> 4;
    const int bmB = blockIdx.y, bx = blockIdx.x;

    float acc[8][4];
#pragma unroll
    for (int r = 0; r < 8; r++)
#pragma unroll
        for (int c = 0; c < 4; c++) acc[r][c] = 0.f;

    for (int kt = 0; kt < KDIM; kt += BK) {
        // fill A tile: 128x16 = 512 float4 slots
#pragma unroll
        for (int i = 0; i < 2; i++) {
            int idx = tid + i * 256;
            int row = idx >> 2;
            int kq  = (idx & 3) << 2;
            float4 va = *(const float4*)&A[(size_t)(bmB * BM + row) * KDIM + kt + kq];
            As[kq + 0][row] = va.x; As[kq + 1][row] = va.y;
            As[kq + 2][row] = va.z; As[kq + 3][row] = va.w;
        }
        // fill B tile: 64x16 = 256 float4 slots
        {
            int row = tid >> 2;
            int kq  = (tid & 3) << 2;
            float4 vb = *(const float4*)&Bw[(size_t)(bx * BN + row) * KDIM + kt + kq];
            Bs[kq + 0][row] = vb.x; Bs[kq + 1][row] = vb.y;
            Bs[kq + 2][row] = vb.z; Bs[kq + 3][row] = vb.w;
        }
        __syncthreads();
#pragma unroll
        for (int k = 0; k < BK; k++) {
            float4 a0 = *(const float4*)&As[k][ty * 4];
            float4 a1 = *(const float4*)&As[k][64 + ty * 4];
            float4 b  = *(const float4*)&Bs[k][tx * 4];
            float av[8] = {a0.x, a0.y, a0.z, a0.w, a1.x, a1.y, a1.z, a1.w};
            float bv[4] = {b.x, b.y, b.z, b.w};
#pragma unroll
            for (int r = 0; r < 8; r++)
#pragma unroll
                for (int c = 0; c < 4; c++) acc[r][c] = fmaf(av[r], bv[c], acc[r][c]);
        }
        __syncthreads();
    }

    // epilogue: bx in 0..35 ; which = bx/12 (0=q,1=k,2=v), h = bx%12
    const int which = bx / HEADS;
    const int h = bx % HEADS;
    const int d0 = tx * 4;
    const float scale = 0.125f;  // 64^-0.5

#pragma unroll
    for (int mm = 0; mm < 2; mm++) {
#pragma unroll
        for (int r = 0; r < 4; r++) {
            int m = bmB * BM + mm * 64 + ty * 4 + r;
            int b_i = m / NTOK, tok = m % NTOK;
            size_t base = ((size_t)(b_i * HEADS + h) * NTOK + tok) * HD + d0;
            float4 o;
            float* accr = acc[mm * 4 + r];
            if (which == 0) {
                o.x = (accr[0] + q_bias[h * HD + d0 + 0]) * scale;
                o.y = (accr[1] + q_bias[h * HD + d0 + 1]) * scale;
                o.z = (accr[2] + q_bias[h * HD + d0 + 2]) * scale;
                o.w = (accr[3] + q_bias[h * HD + d0 + 3]) * scale;
                *(float4*)&g_q[base] = o;
            } else if (which == 1) {
                o.x = accr[0]; o.y = accr[1]; o.z = accr[2]; o.w = accr[3];
                *(float4*)&g_k[base] = o;
            } else {
                o.x = accr[0] + v_bias[h * HD + d0 + 0];
                o.y = accr[1] + v_bias[h * HD + d0 + 1];
                o.z = accr[2] + v_bias[h * HD + d0 + 2];
                o.w = accr[3] + v_bias[h * HD + d0 + 3];
                *(float4*)&g_v[base] = o;
            }
        }
    }
}

// ======================= SGEMM: output projection =======================
__global__ __launch_bounds__(256)
void proj_gemm_kernel(const float* __restrict__ Bw, const float* __restrict__ bias,
                      float* __restrict__ out) {
    __shared__ float As[BK][BM + 4];
    __shared__ float Bs[BK][BN + 4];

    const int tid = threadIdx.x;
    const int tx = tid & 15, ty = tid >> 4;
    const int bmB = blockIdx.y, bx = blockIdx.x;

    float acc[8][4];
#pragma unroll
    for (int r = 0; r < 8; r++)
#pragma unroll
        for (int c = 0; c < 4; c++) acc[r][c] = 0.f;

    for (int kt = 0; kt < KDIM; kt += BK) {
#pragma unroll
        for (int i = 0; i < 2; i++) {
            int idx = tid + i * 256;
            int row = idx >> 2;
            int kq  = (idx & 3) << 2;
            float4 va = *(const float4*)&g_ao[(size_t)(bmB * BM + row) * KDIM + kt + kq];
            As[kq + 0][row] = va.x; As[kq + 1][row] = va.y;
            As[kq + 2][row] = va.z; As[kq + 3][row] = va.w;
        }
        {
            int row = tid >> 2;
            int kq  = (tid & 3) << 2;
            float4 vb = *(const float4*)&Bw[(size_t)(bx * BN + row) * KDIM + kt + kq];
            Bs[kq + 0][row] = vb.x; Bs[kq + 1][row] = vb.y;
            Bs[kq + 2][row] = vb.z; Bs[kq + 3][row] = vb.w;
        }
        __syncthreads();
#pragma unroll
        for (int k = 0; k < BK; k++) {
            float4 a0 = *(const float4*)&As[k][ty * 4];
            float4 a1 = *(const float4*)&As[k][64 + ty * 4];
            float4 b  = *(const float4*)&Bs[k][tx * 4];
            float av[8] = {a0.x, a0.y, a0.z, a0.w, a1.x, a1.y, a1.z, a1.w};
            float bv[4] = {b.x, b.y, b.z, b.w};
#pragma unroll
            for (int r = 0; r < 8; r++)
#pragma unroll
                for (int c = 0; c < 4; c++) acc[r][c] = fmaf(av[r], bv[c], acc[r][c]);
        }
        __syncthreads();
    }

    const int gn0 = bx * BN + tx * 4;
    float4 bb = *(const float4*)&bias[gn0];
#pragma unroll
    for (int mm = 0; mm < 2; mm++) {
#pragma unroll
        for (int r = 0; r < 4; r++) {
            int m = bmB * BM + mm * 64 + ty * 4 + r;
            float4 o;
            float* accr = acc[mm * 4 + r];
            o.x = accr[0] + bb.x; o.y = accr[1] + bb.y;
            o.z = accr[2] + bb.z; o.w = accr[3] + bb.w;
            *(float4*)&out[(size_t)m * CDIM + gn0] = o;
        }
    }
}

// ======================= attention (per (b,h) CTA, K/V in smem) =======================
// NOTE: writes g_ao via the device-side symbol directly. Passing g_ao as a
// host-side kernel argument was the R1 bug (host shadow address, not device).
#define KPAD 68                          // 197 rows x 68 floats (conflict-free f4 reads)
#define SM_K  (NTOK * KPAD)              // 13396 floats
#define SM_V  (NTOK * HD)                // 12608
#define SM_P  (8 * 200)                  // 1600
#define SM_Q  (8 * HD)                   // 512
#define SMEM_ATTN ((SM_K + SM_V + SM_P + SM_Q) * 4)   // 112464 bytes

__global__ __launch_bounds__(256)
void attn_kernel() {
    extern __shared__ float sm[];
    float* Ks = sm;
    float* Vs = Ks + SM_K;
    float* Ps = Vs + SM_V;
    float* Qs = Ps + SM_P;

    const int bh = blockIdx.x;
    const int b = bh / HEADS, h = bh % HEADS;
    const int tid = threadIdx.x;
    const float* kb = g_k + (size_t)bh * NTOK * HD;
    const float* vb = g_v + (size_t)bh * NTOK * HD;
    const float* qg = g_q + (size_t)bh * NTOK * HD;
    const float* rb = g_rb + (size_t)h * NTOK * NTOK;

    // fill K (padded) and V (dense) tiles
    for (int e = tid; e < NTOK * (HD / 4); e += 256) {
        int row = e >> 4, c4 = (e & 15) << 2;
        float4 kv = *(const float4*)&kb[row * HD + c4];
        *(float4*)&Ks[row * KPAD + c4] = kv;
        float4 vv = *(const float4*)&vb[row * HD + c4];
        *(float4*)&Vs[row * HD + c4] = vv;
    }
    __syncthreads();

    const int w = tid >> 5, lane = tid & 31;
    for (int q = w; q < NTOK; q += 8) {
        // stage this query into per-warp smem
        float2 qv = *(const float2*)&qg[(size_t)q * HD + lane * 2];
        *(float2*)&Qs[w * HD + lane * 2] = qv;
        __syncwarp();

        float s[7];
#pragma unroll
        for (int i = 0; i < 7; i++) {
            int m = lane + i * 32;
            if (m < NTOK) {
                float acc = 0.f;
#pragma unroll
                for (int d4 = 0; d4 < 16; d4++) {
                    float4 kk = *(const float4*)&Ks[m * KPAD + d4 * 4];
                    float4 qq = *(const float4*)&Qs[w * HD + d4 * 4];
                    acc = fmaf(kk.x, qq.x, acc);
                    acc = fmaf(kk.y, qq.y, acc);
                    acc = fmaf(kk.z, qq.z, acc);
                    acc = fmaf(kk.w, qq.w, acc);
                }
                s[i] = acc + rb[(size_t)q * NTOK + m];
            } else {
                s[i] = -1e30f;
            }
        }
        // softmax within warp
        float mx = s[0];
#pragma unroll
        for (int i = 1; i < 7; i++) mx = fmaxf(mx, s[i]);
#pragma unroll
        for (int o = 16; o > 0; o >>= 1) mx = fmaxf(mx, __shfl_xor_sync(0xffffffffu, mx, o));
        float sum = 0.f;
#pragma unroll
        for (int i = 0; i < 7; i++) {
            int m = lane + i * 32;
            s[i] = (m < NTOK) ? __expf(s[i] - mx) : 0.f;
            sum += s[i];
        }
#pragma unroll
        for (int o = 16; o > 0; o >>= 1) sum += __shfl_xor_sync(0xffffffffu, sum, o);
        float inv = 1.f / sum;
#pragma unroll
        for (int i = 0; i < 7; i++) {
            int m = lane + i * 32;
            if (m < NTOK) Ps[w * 200 + m] = s[i] * inv;
        }
        __syncwarp();

        // out[d] = sum_m p[m] * V[m][d], d distributed over lanes (2 each)
        float2 o2 = {0.f, 0.f};
        for (int m = 0; m < NTOK; m++) {
            float pm = Ps[w * 200 + m];
            float2 vv = *(const float2*)&Vs[m * HD + lane * 2];
            o2.x = fmaf(pm, vv.x, o2.x);
            o2.y = fmaf(pm, vv.y, o2.y);
        }
        // write via device-side symbol (fixes R1 host-shadow-pointer bug)
        *(float2*)&g_ao[((size_t)(b * NTOK + q)) * CDIM + h * HD + lane * 2] = o2;
        __syncwarp();
    }
}

// ======================= launch =======================
extern "C" void kernel_launch(void* const* d_in, const int* in_sizes, int n_in,
                              void* d_out, int out_size) {
    const float* x        = (const float*)d_in[0];
    const float* qkv_w    = (const float*)d_in[1];
    const float* q_bias   = (const float*)d_in[2];
    const float* v_bias   = (const float*)d_in[3];
    const float* rel_tab  = (const float*)d_in[4];
    const float* proj_w   = (const float*)d_in[5];
    const float* proj_b   = (const float*)d_in[6];
    const int*   rel_idx  = (const int*)d_in[7];
    float* out = (float*)d_out;

    static_assert(MROWS % BM == 0, "M tiling");

    static bool attr_set = false;
    if (!attr_set) {
        cudaFuncSetAttribute(attn_kernel, cudaFuncAttributeMaxDynamicSharedMemorySize, SMEM_ATTN);
        attr_set = true;
    }

    // 1. relative position bias gather
    relbias_kernel<<<(NTOK * NTOK + 255) / 256, 256>>>(rel_tab, rel_idx);

    // 2. QKV projection (writes g_q/g_k/g_v, scaled q)
    {
        dim3 grid(N_QKV / BN, MROWS / BM);  // (36, 197)
        qkv_gemm_kernel<<<grid, 256>>>(x, qkv_w, q_bias, v_bias);
    }

    // 3. attention (writes g_ao internally)
    attn_kernel<<<BATCH * HEADS, 256, SMEM_ATTN>>>();

    // 4. output projection
    {
        dim3 grid(CDIM / BN, MROWS / BM);  // (12, 197)
        proj_gemm_kernel<<<grid, 256>>>(proj_w, proj_b, out);
    }
}

// round 3
// speedup vs baseline: 1.0182x; 1.0182x over previous
#include <cuda_runtime.h>
#include <cuda_bf16.h>

// Problem constants
#define BATCH 128
#define HEADS 12
#define NTOK  197
#define CDIM  768
#define HD    64
#define MROWS (BATCH * NTOK) // 25216
#define KDIM  768
#define N_QKV (3 * CDIM)     // 2304

// -------- scratch --------
__device__ float g_q [BATCH * HEADS * NTOK * HD];
__device__ float g_k [BATCH * HEADS * NTOK * HD];
__device__ float g_v [BATCH * HEADS * NTOK * HD];
__device__ float g_rb[HEADS * NTOK * NTOK];
__device__ float g_ao[BATCH * NTOK * CDIM];

// ======================= rel-pos bias gather =======================
__global__ void relbias_kernel(const float* __restrict__ table,
                               const int* __restrict__ idx) {
    int i = blockIdx.x * 256 + threadIdx.x;
    if (i < NTOK * NTOK) {
        int id = idx[i];
#pragma unroll
        for (int h = 0; h < HEADS; h++)
            g_rb[h * NTOK * NTOK + i] = table[id * HEADS + h];
    }
}

// ======================= tf32 tensor-core GEMM (3xTF32 split) =======================
// C[m,n] = sum_k A[m,k] * B[n,k]   (both row-major, K contiguous)
// CTA tile 128(M) x 64(N) x 32(K); 8 warps in 4(M) x 2(N); warp tile 32x32.
// Each element stored in smem as float2 {big, small}: big = tf32(v), small = tf32(v-big).
// 3 MMA passes: big*big + big*small + small*big  -> ~fp32 accuracy.
#define GBM 128
#define GBN 64
#define GBK 32
#define GSTR 36                    // row stride in float2 units (conflict-free frags)
#define GA_F2 (GBM * GSTR)         // 4608
#define GB_F2 (GBN * GSTR)         // 2304
#define SMEM_GEMM ((GA_F2 + GB_F2) * 8)   // 55296 bytes

__device__ __forceinline__ float2 split_tf32(float v) {
    unsigned bi; asm("cvt.rna.tf32.f32 %0, %1;" : "=r"(bi) : "f"(v));
    float big = __uint_as_float(bi);
    float sm = v - big;
    unsigned si; asm("cvt.rna.tf32.f32 %0, %1;" : "=r"(si) : "f"(sm));
    return make_float2(big, __uint_as_float(si));
}

__device__ __forceinline__ void mma8(float* c, const unsigned* a, const unsigned* b) {
    asm volatile("mma.sync.aligned.m16n8k8.row.col.f32.tf32.tf32.f32 "
        "{%0,%1,%2,%3}, {%4,%5,%6,%7}, {%8,%9}, {%0,%1,%2,%3};"
        : "+f"(c[0]), "+f"(c[1]), "+f"(c[2]), "+f"(c[3])
        : "r"(a[0]), "r"(a[1]), "r"(a[2]), "r"(a[3]), "r"(b[0]), "r"(b[1]));
}

// Shared mainloop: fills acc[2][4][4] for this thread's warp-tile fragment.
__device__ __forceinline__ void gemm_mainloop(
    const float* __restrict__ A, const float* __restrict__ Bw,
    int m0, int n0, float2* As2, float2* Bs2, float acc[2][4][4]) {

    const int tid = threadIdx.x;
    const int lane = tid & 31, warp = tid >> 5;
    const int tig = lane & 3, gid = lane >> 2;
    const int mbase = (warp & 3) * 32;   // warp M offset
    const int nbase = (warp >> 2) * 32;  // warp N offset

#pragma unroll
    for (int a = 0; a < 2; a++)
#pragma unroll
        for (int b = 0; b < 4; b++)
#pragma unroll
            for (int c = 0; c < 4; c++) acc[a][b][c] = 0.f;

    for (int kt = 0; kt < KDIM; kt += GBK) {
        // ---- fill A tile: 128 rows x 8 float4 = 1024 f4, 4 per thread ----
#pragma unroll
        for (int i = 0; i < 4; i++) {
            int idx = i * 256 + tid;
            int row = idx >> 3, j = idx & 7;
            float4 v = *(const float4*)&A[(size_t)(m0 + row) * KDIM + kt + j * 4];
            float2 s0 = split_tf32(v.x), s1 = split_tf32(v.y);
            float2 s2 = split_tf32(v.z), s3 = split_tf32(v.w);
            float4* p = (float4*)&As2[row * GSTR + j * 4];
            p[0] = make_float4(s0.x, s0.y, s1.x, s1.y);
            p[1] = make_float4(s2.x, s2.y, s3.x, s3.y);
        }
        // ---- fill B tile: 64 rows x 8 f4 = 512 f4, 2 per thread ----
#pragma unroll
        for (int i = 0; i < 2; i++) {
            int idx = i * 256 + tid;
            int row = idx >> 3, j = idx & 7;
            float4 v = *(const float4*)&Bw[(size_t)(n0 + row) * KDIM + kt + j * 4];
            float2 s0 = split_tf32(v.x), s1 = split_tf32(v.y);
            float2 s2 = split_tf32(v.z), s3 = split_tf32(v.w);
            float4* p = (float4*)&Bs2[row * GSTR + j * 4];
            p[0] = make_float4(s0.x, s0.y, s1.x, s1.y);
            p[1] = make_float4(s2.x, s2.y, s3.x, s3.y);
        }
        __syncthreads();

#pragma unroll
        for (int kk = 0; kk < GBK / 8; kk++) {
            const int kb = kk * 8;
            unsigned Ab[2][4], Asm[2][4], Bb[4][2], Bsm[4][2];
#pragma unroll
            for (int mt = 0; mt < 2; mt++) {
                int m = mbase + mt * 16;
                float2 f0 = As2[(m + gid) * GSTR + kb + tig];
                float2 f1 = As2[(m + 8 + gid) * GSTR + kb + tig];
                float2 f2 = As2[(m + gid) * GSTR + kb + 4 + tig];
                float2 f3 = As2[(m + 8 + gid) * GSTR + kb + 4 + tig];
                Ab[mt][0] = __float_as_uint(f0.x); Asm[mt][0] = __float_as_uint(f0.y);
                Ab[mt][1] = __float_as_uint(f1.x); Asm[mt][1] = __float_as_uint(f1.y);
                Ab[mt][2] = __float_as_uint(f2.x); Asm[mt][2] = __float_as_uint(f2.y);
                Ab[mt][3] = __float_as_uint(f3.x); Asm[mt][3] = __float_as_uint(f3.y);
            }
#pragma unroll
            for (int nt = 0; nt < 4; nt++) {
                int n = nbase + nt * 8;
                float2 f0 = Bs2[(n + gid) * GSTR + kb + tig];
                float2 f1 = Bs2[(n + gid) * GSTR + kb + 4 + tig];
                Bb[nt][0] = __float_as_uint(f0.x); Bsm[nt][0] = __float_as_uint(f0.y);
                Bb[nt][1] = __float_as_uint(f1.x); Bsm[nt][1] = __float_as_uint(f1.y);
            }
#pragma unroll
            for (int mt = 0; mt < 2; mt++)
#pragma unroll
                for (int nt = 0; nt < 4; nt++) {
                    mma8(acc[mt][nt], Ab[mt], Bb[nt]);   // big * big
                    mma8(acc[mt][nt], Ab[mt], Bsm[nt]);  // big * small
                    mma8(acc[mt][nt], Asm[mt], Bb[nt]);  // small * big
                }
        }
        __syncthreads();
    }
}

// ---- QKV GEMM: N=2304 split into (which, head); scatter with bias+scale ----
__global__ __launch_bounds__(256, 2)
void qkv_gemm_kernel(const float* __restrict__ A, const float* __restrict__ Bw,
                     const float* __restrict__ q_bias, const float* __restrict__ v_bias) {
    extern __shared__ float2 sm2[];
    float2* As2 = sm2;
    float2* Bs2 = sm2 + GA_F2;

    const int bx = blockIdx.x, m0 = blockIdx.y * GBM;
    const int n0 = bx * GBN;
    float acc[2][4][4];
    gemm_mainloop(A, Bw, m0, n0, As2, Bs2, acc);

    const int lane = threadIdx.x & 31, warp = threadIdx.x >> 5;
    const int tig = lane & 3, gid = lane >> 2;
    const int mbase = (warp & 3) * 32, nbase = (warp >> 2) * 32;
    const int which = bx / HEADS, h = bx % HEADS;
    const float scale = 0.125f;

#pragma unroll
    for (int mt = 0; mt < 2; mt++)
#pragma unroll
        for (int nt = 0; nt < 4; nt++) {
            int d = nbase + nt * 8 + tig * 2;       // 0..62, within head dim 64
#pragma unroll
            for (int half = 0; half < 2; half++) {
                int m = m0 + mbase + mt * 16 + gid + half * 8;
                int b_i = m / NTOK, tok = m % NTOK;
                size_t base = ((size_t)(b_i * HEADS + h) * NTOK + tok) * HD + d;
                float2 o = make_float2(acc[mt][nt][half * 2 + 0], acc[mt][nt][half * 2 + 1]);
                if (which == 0) {
                    float2 qb = *(const float2*)&q_bias[h * HD + d];
                    o.x = (o.x + qb.x) * scale;
                    o.y = (o.y + qb.y) * scale;
                    *(float2*)&g_q[base] = o;
                } else if (which == 1) {
                    *(float2*)&g_k[base] = o;
                } else {
                    float2 vb = *(const float2*)&v_bias[h * HD + d];
                    o.x += vb.x; o.y += vb.y;
                    *(float2*)&g_v[base] = o;
                }
            }
        }
}

// ---- output projection GEMM ----
__global__ __launch_bounds__(256, 2)
void proj_gemm_kernel(const float* __restrict__ Bw, const float* __restrict__ bias,
                      float* __restrict__ out) {
    extern __shared__ float2 sm2[];
    float2* As2 = sm2;
    float2* Bs2 = sm2 + GA_F2;

    const int bx = blockIdx.x, m0 = blockIdx.y * GBM;
    const int n0 = bx * GBN;
    float acc[2][4][4];
    gemm_mainloop(g_ao, Bw, m0, n0, As2, Bs2, acc);

    const int lane = threadIdx.x & 31, warp = threadIdx.x >> 5;
    const int tig = lane & 3, gid = lane >> 2;
    const int mbase = (warp & 3) * 32, nbase = (warp >> 2) * 32;

#pragma unroll
    for (int mt = 0; mt < 2; mt++)
#pragma unroll
        for (int nt = 0; nt < 4; nt++) {
            int ng = n0 + nbase + nt * 8 + tig * 2;
            float2 bb = *(const float2*)&bias[ng];
#pragma unroll
            for (int half = 0; half < 2; half++) {
                int m = m0 + mbase + mt * 16 + gid + half * 8;
                float2 o = make_float2(acc[mt][nt][half * 2 + 0] + bb.x,
                                       acc[mt][nt][half * 2 + 1] + bb.y);
                *(float2*)&out[(size_t)m * CDIM + ng] = o;
            }
        }
}

// ======================= attention (unchanged from R2) =======================
#define KPAD 68
#define SM_K  (NTOK * KPAD)
#define SM_V  (NTOK * HD)
#define SM_P  (8 * 200)
#define SM_Q  (8 * HD)
#define SMEM_ATTN ((SM_K + SM_V + SM_P + SM_Q) * 4)

__global__ __launch_bounds__(256)
void attn_kernel() {
    extern __shared__ float sm[];
    float* Ks = sm;
    float* Vs = Ks + SM_K;
    float* Ps = Vs + SM_V;
    float* Qs = Ps + SM_P;

    const int bh = blockIdx.x;
    const int b = bh / HEADS, h = bh % HEADS;
    const int tid = threadIdx.x;
    const float* kb = g_k + (size_t)bh * NTOK * HD;
    const float* vb = g_v + (size_t)bh * NTOK * HD;
    const float* qg = g_q + (size_t)bh * NTOK * HD;
    const float* rb = g_rb + (size_t)h * NTOK * NTOK;

    for (int e = tid; e < NTOK * (HD / 4); e += 256) {
        int row = e >> 4, c4 = (e & 15) << 2;
        float4 kv = *(const float4*)&kb[row * HD + c4];
        *(float4*)&Ks[row * KPAD + c4] = kv;
        float4 vv = *(const float4*)&vb[row * HD + c4];
        *(float4*)&Vs[row * HD + c4] = vv;
    }
    __syncthreads();

    const int w = tid >> 5, lane = tid & 31;
    for (int q = w; q < NTOK; q += 8) {
        float2 qv = *(const float2*)&qg[(size_t)q * HD + lane * 2];
        *(float2*)&Qs[w * HD + lane * 2] = qv;
        __syncwarp();

        float s[7];
#pragma unroll
        for (int i = 0; i < 7; i++) {
            int m = lane + i * 32;
            if (m < NTOK) {
                float acc = 0.f;
#pragma unroll
                for (int d4 = 0; d4 < 16; d4++) {
                    float4 kk = *(const float4*)&Ks[m * KPAD + d4 * 4];
                    float4 qq = *(const float4*)&Qs[w * HD + d4 * 4];
                    acc = fmaf(kk.x, qq.x, acc);
                    acc = fmaf(kk.y, qq.y, acc);
                    acc = fmaf(kk.z, qq.z, acc);
                    acc = fmaf(kk.w, qq.w, acc);
                }
                s[i] = acc + rb[(size_t)q * NTOK + m];
            } else {
                s[i] = -1e30f;
            }
        }
        float mx = s[0];
#pragma unroll
        for (int i = 1; i < 7; i++) mx = fmaxf(mx, s[i]);
#pragma unroll
        for (int o = 16; o > 0; o >>= 1) mx = fmaxf(mx, __shfl_xor_sync(0xffffffffu, mx, o));
        float sum = 0.f;
#pragma unroll
        for (int i = 0; i < 7; i++) {
            int m = lane + i * 32;
            s[i] = (m < NTOK) ? __expf(s[i] - mx) : 0.f;
            sum += s[i];
        }
#pragma unroll
        for (int o = 16; o > 0; o >>= 1) sum += __shfl_xor_sync(0xffffffffu, sum, o);
        float inv = 1.f / sum;
#pragma unroll
        for (int i = 0; i < 7; i++) {
            int m = lane + i * 32;
            if (m < NTOK) Ps[w * 200 + m] = s[i] * inv;
        }
        __syncwarp();

        float2 o2 = {0.f, 0.f};
        for (int m = 0; m < NTOK; m++) {
            float pm = Ps[w * 200 + m];
            float2 vv = *(const float2*)&Vs[m * HD + lane * 2];
            o2.x = fmaf(pm, vv.x, o2.x);
            o2.y = fmaf(pm, vv.y, o2.y);
        }
        *(float2*)&g_ao[((size_t)(b * NTOK + q)) * CDIM + h * HD + lane * 2] = o2;
        __syncwarp();
    }
}

// ======================= launch =======================
extern "C" void kernel_launch(void* const* d_in, const int* in_sizes, int n_in,
                              void* d_out, int out_size) {
    const float* x        = (const float*)d_in[0];
    const float* qkv_w    = (const float*)d_in[1];
    const float* q_bias   = (const float*)d_in[2];
    const float* v_bias   = (const float*)d_in[3];
    const float* rel_tab  = (const float*)d_in[4];
    const float* proj_w   = (const float*)d_in[5];
    const float* proj_b   = (const float*)d_in[6];
    const int*   rel_idx  = (const int*)d_in[7];
    float* out = (float*)d_out;

    static_assert(MROWS % GBM == 0, "M tiling");
    static_assert(N_QKV % GBN == 0 && CDIM % GBN == 0, "N tiling");

    cudaFuncSetAttribute(qkv_gemm_kernel,  cudaFuncAttributeMaxDynamicSharedMemorySize, SMEM_GEMM);
    cudaFuncSetAttribute(proj_gemm_kernel, cudaFuncAttributeMaxDynamicSharedMemorySize, SMEM_GEMM);
    cudaFuncSetAttribute(attn_kernel,      cudaFuncAttributeMaxDynamicSharedMemorySize, SMEM_ATTN);

    relbias_kernel<<<(NTOK * NTOK + 255) / 256, 256>>>(rel_tab, rel_idx);

    {
        dim3 grid(N_QKV / GBN, MROWS / GBM);  // (36, 197)
        qkv_gemm_kernel<<<grid, 256, SMEM_GEMM>>>(x, qkv_w, q_bias, v_bias);
    }

    attn_kernel<<<BATCH * HEADS, 256, SMEM_ATTN>>>();

    {
        dim3 grid(CDIM / GBN, MROWS / GBM);   // (12, 197)
        proj_gemm_kernel<<<grid, 256, SMEM_GEMM>>>(proj_w, proj_b, out);
    }
}

// round 5
// speedup vs baseline: 1.4962x; 1.4694x over previous
#include <cuda_runtime.h>
#include <cuda_bf16.h>

// Problem constants
#define BATCH 128
#define HEADS 12
#define NTOK  197
#define CDIM  768
#define HD    64
#define MROWS (BATCH * NTOK) // 25216
#define KDIM  768
#define N_QKV (3 * CDIM)     // 2304

// -------- fp32 scratch --------
__device__ float g_q [BATCH * HEADS * NTOK * HD];
__device__ float g_k [BATCH * HEADS * NTOK * HD];
__device__ float g_v [BATCH * HEADS * NTOK * HD];
__device__ float g_rb[HEADS * NTOK * NTOK];

// -------- bf16 split scratch (big/small pairs) --------
__device__ __nv_bfloat16 g_xb [MROWS * KDIM];
__device__ __nv_bfloat16 g_xs [MROWS * KDIM];
__device__ __nv_bfloat16 g_wqb[N_QKV * KDIM];
__device__ __nv_bfloat16 g_wqs[N_QKV * KDIM];
__device__ __nv_bfloat16 g_wpb[CDIM * CDIM];
__device__ __nv_bfloat16 g_wps[CDIM * CDIM];
__device__ __nv_bfloat16 g_aob[MROWS * CDIM];
__device__ __nv_bfloat16 g_aos[MROWS * CDIM];

// ======================= rel-pos bias gather =======================
__global__ void relbias_kernel(const float* __restrict__ table,
                               const int* __restrict__ idx) {
    int i = blockIdx.x * 256 + threadIdx.x;
    if (i < NTOK * NTOK) {
        int id = idx[i];
#pragma unroll
        for (int h = 0; h < HEADS; h++)
            g_rb[h * NTOK * NTOK + i] = table[id * HEADS + h];
    }
}

// ======================= fp32 -> bf16{big,small} split =======================
__device__ __forceinline__ void split1(float v, __nv_bfloat16& b, __nv_bfloat16& s) {
    b = __float2bfloat16_rn(v);
    s = __float2bfloat16_rn(v - __bfloat162float(b));
}

__global__ void split_kernel(const float* __restrict__ src,
                             __nv_bfloat16* __restrict__ big,
                             __nv_bfloat16* __restrict__ small, int n4) {
    int i = blockIdx.x * 256 + threadIdx.x;
    if (i < n4) {
        float4 v = *(const float4*)&src[i * 4];
        __nv_bfloat16 b0,s0,b1,s1,b2,s2,b3,s3;
        split1(v.x,b0,s0); split1(v.y,b1,s1); split1(v.z,b2,s2); split1(v.w,b3,s3);
        *(__nv_bfloat162*)&big  [i*4    ] = {b0,b1};
        *(__nv_bfloat162*)&big  [i*4 + 2] = {b2,b3};
        *(__nv_bfloat162*)&small[i*4    ] = {s0,s1};
        *(__nv_bfloat162*)&small[i*4 + 2] = {s2,s3};
    }
}

// ======================= bf16 3-pass tensor-core GEMM =======================
// C[m,n] = sum_k A[m,k]*B[n,k], K contiguous. CTA 128x64x32, 8 warps (4Mx2N),
// warp tile 32x32. Pre-split operands; 3 MMA passes: bb + bs + sb.
#define GBM 128
#define GBN 64
#define GBK 32
#define GSTR 40   // smem row stride in bf16 (80B, conflict-free .b32 frags)
#define SA_ELEM (GBM * GSTR)
#define SB_ELEM (GBN * GSTR)
#define SMEM_GEMM ((2 * SA_ELEM + 2 * SB_ELEM) * 2)  // 30720 B

__device__ __forceinline__ void mma16(float* c, const unsigned* a, const unsigned* b) {
    asm volatile("mma.sync.aligned.m16n8k16.row.col.f32.bf16.bf16.f32 "
        "{%0,%1,%2,%3}, {%4,%5,%6,%7}, {%8,%9}, {%0,%1,%2,%3};"
        : "+f"(c[0]), "+f"(c[1]), "+f"(c[2]), "+f"(c[3])
        : "r"(a[0]), "r"(a[1]), "r"(a[2]), "r"(a[3]), "r"(b[0]), "r"(b[1]));
}

__device__ __forceinline__ void gemm_mainloop(
    const __nv_bfloat16* __restrict__ Ab, const __nv_bfloat16* __restrict__ Asml,
    const __nv_bfloat16* __restrict__ Bb, const __nv_bfloat16* __restrict__ Bsml,
    int m0, int n0, __nv_bfloat16* sm, float acc[2][4][4]) {

    __nv_bfloat16* As_b = sm;
    __nv_bfloat16* As_s = sm + SA_ELEM;
    __nv_bfloat16* Bs_b = sm + 2 * SA_ELEM;
    __nv_bfloat16* Bs_s = sm + 2 * SA_ELEM + SB_ELEM;

    const int tid = threadIdx.x;
    const int lane = tid & 31, warp = tid >> 5;
    const int tig = lane & 3, gid = lane >> 2;
    const int mbase = (warp & 3) * 32;
    const int nbase = (warp >> 2) * 32;

#pragma unroll
    for (int a = 0; a < 2; a++)
#pragma unroll
        for (int b = 0; b < 4; b++)
#pragma unroll
            for (int c = 0; c < 4; c++) acc[a][b][c] = 0.f;

    for (int kt = 0; kt < KDIM; kt += GBK) {
        // A tiles: 128 rows x 32 bf16 = 512 uint4 per buffer, 2 per thread each
#pragma unroll
        for (int i = 0; i < 2; i++) {
            int idx = i * 256 + tid;
            int row = idx >> 2, j = idx & 3;
            size_t gsrc = (size_t)(m0 + row) * KDIM + kt + j * 8;
            *(uint4*)&As_b[row * GSTR + j * 8] = *(const uint4*)&Ab[gsrc];
            *(uint4*)&As_s[row * GSTR + j * 8] = *(const uint4*)&Asml[gsrc];
        }
        // B tiles: 64 rows -> 256 uint4 per buffer, 1 per thread each
        {
            int row = tid >> 2, j = tid & 3;
            size_t gsrc = (size_t)(n0 + row) * KDIM + kt + j * 8;
            *(uint4*)&Bs_b[row * GSTR + j * 8] = *(const uint4*)&Bb[gsrc];
            *(uint4*)&Bs_s[row * GSTR + j * 8] = *(const uint4*)&Bsml[gsrc];
        }
        __syncthreads();

#pragma unroll
        for (int kk = 0; kk < GBK / 16; kk++) {
            const int kb = kk * 16;
            unsigned Afb[2][4], Afs[2][4], Bfb[4][2], Bfs[4][2];
#pragma unroll
            for (int mt = 0; mt < 2; mt++) {
                int r0 = (mbase + mt * 16 + gid) * GSTR;
                int r8 = r0 + 8 * GSTR;
                int c0 = kb + tig * 2, c8 = c0 + 8;
                Afb[mt][0] = *(const unsigned*)&As_b[r0 + c0];
                Afb[mt][1] = *(const unsigned*)&As_b[r8 + c0];
                Afb[mt][2] = *(const unsigned*)&As_b[r0 + c8];
                Afb[mt][3] = *(const unsigned*)&As_b[r8 + c8];
                Afs[mt][0] = *(const unsigned*)&As_s[r0 + c0];
                Afs[mt][1] = *(const unsigned*)&As_s[r8 + c0];
                Afs[mt][2] = *(const unsigned*)&As_s[r0 + c8];
                Afs[mt][3] = *(const unsigned*)&As_s[r8 + c8];
            }
#pragma unroll
            for (int nt = 0; nt < 4; nt++) {
                int r = (nbase + nt * 8 + gid) * GSTR;
                int c0 = kb + tig * 2, c8 = c0 + 8;
                Bfb[nt][0] = *(const unsigned*)&Bs_b[r + c0];
                Bfb[nt][1] = *(const unsigned*)&Bs_b[r + c8];
                Bfs[nt][0] = *(const unsigned*)&Bs_s[r + c0];
                Bfs[nt][1] = *(const unsigned*)&Bs_s[r + c8];
            }
#pragma unroll
            for (int mt = 0; mt < 2; mt++)
#pragma unroll
                for (int nt = 0; nt < 4; nt++) {
                    mma16(acc[mt][nt], Afb[mt], Bfb[nt]);  // big*big
                    mma16(acc[mt][nt], Afb[mt], Bfs[nt]);  // big*small
                    mma16(acc[mt][nt], Afs[mt], Bfb[nt]);  // small*big
                }
        }
        __syncthreads();
    }
}

// ---- QKV GEMM ----
__global__ __launch_bounds__(256, 2)
void qkv_gemm_kernel(const float* __restrict__ q_bias, const float* __restrict__ v_bias) {
    extern __shared__ __nv_bfloat16 smg[];
    const int bx = blockIdx.x, m0 = blockIdx.y * GBM;
    float acc[2][4][4];
    gemm_mainloop(g_xb, g_xs, g_wqb, g_wqs, m0, bx * GBN, smg, acc);

    const int lane = threadIdx.x & 31, warp = threadIdx.x >> 5;
    const int tig = lane & 3, gid = lane >> 2;
    const int mbase = (warp & 3) * 32, nbase = (warp >> 2) * 32;
    const int which = bx / HEADS, h = bx % HEADS;
    const float scale = 0.125f;

#pragma unroll
    for (int mt = 0; mt < 2; mt++)
#pragma unroll
        for (int nt = 0; nt < 4; nt++) {
            int d = nbase + nt * 8 + tig * 2;
#pragma unroll
            for (int half = 0; half < 2; half++) {
                int m = m0 + mbase + mt * 16 + gid + half * 8;
                int b_i = m / NTOK, tok = m % NTOK;
                size_t base = ((size_t)(b_i * HEADS + h) * NTOK + tok) * HD + d;
                float2 o = make_float2(acc[mt][nt][half * 2 + 0], acc[mt][nt][half * 2 + 1]);
                if (which == 0) {
                    float2 qb = *(const float2*)&q_bias[h * HD + d];
                    o.x = (o.x + qb.x) * scale;
                    o.y = (o.y + qb.y) * scale;
                    *(float2*)&g_q[base] = o;
                } else if (which == 1) {
                    *(float2*)&g_k[base] = o;
                } else {
                    float2 vb = *(const float2*)&v_bias[h * HD + d];
                    o.x += vb.x; o.y += vb.y;
                    *(float2*)&g_v[base] = o;
                }
            }
        }
}

// ---- output projection GEMM ----
__global__ __launch_bounds__(256, 2)
void proj_gemm_kernel(const float* __restrict__ bias, float* __restrict__ out) {
    extern __shared__ __nv_bfloat16 smg[];
    const int bx = blockIdx.x, m0 = blockIdx.y * GBM;
    float acc[2][4][4];
    gemm_mainloop(g_aob, g_aos, g_wpb, g_wps, m0, bx * GBN, smg, acc);

    const int lane = threadIdx.x & 31, warp = threadIdx.x >> 5;
    const int tig = lane & 3, gid = lane >> 2;
    const int mbase = (warp & 3) * 32, nbase = (warp >> 2) * 32;

#pragma unroll
    for (int mt = 0; mt < 2; mt++)
#pragma unroll
        for (int nt = 0; nt < 4; nt++) {
            int ng = bx * GBN + nbase + nt * 8 + tig * 2;
            float2 bb = *(const float2*)&bias[ng];
#pragma unroll
            for (int half = 0; half < 2; half++) {
                int m = m0 + mbase + mt * 16 + gid + half * 8;
                float2 o = make_float2(acc[mt][nt][half * 2 + 0] + bb.x,
                                       acc[mt][nt][half * 2 + 1] + bb.y);
                *(float2*)&out[(size_t)m * CDIM + ng] = o;
            }
        }
}

// ======================= attention (q-blocked SIMT) =======================
#define QBLK 4
#define NQG  ((NTOK + QBLK - 1) / QBLK)  // 50
#define KPAD 68
#define PSTR 5
#define SM_K (NTOK * KPAD)               // 13396
#define SM_V (NTOK * HD)                 // 12608
#define SM_P (8 * 200 * PSTR)            // 8000
#define SM_Q (8 * QBLK * HD)             // 2048
#define SMEM_ATTN ((SM_K + SM_V + SM_P + SM_Q) * 4)  // 144208 B

__global__ __launch_bounds__(256)
void attn_kernel() {
    extern __shared__ float sm[];
    float* Ks = sm;
    float* Vs = Ks + SM_K;
    float* Ps = Vs + SM_V;
    float* Qs = Ps + SM_P;

    const int bh = blockIdx.x;
    const int b = bh / HEADS, h = bh % HEADS;
    const int tid = threadIdx.x;
    const float* kb = g_k + (size_t)bh * NTOK * HD;
    const float* vb = g_v + (size_t)bh * NTOK * HD;
    const float* qg = g_q + (size_t)bh * NTOK * HD;
    const float* rb = g_rb + (size_t)h * NTOK * NTOK;

    for (int e = tid; e < NTOK * (HD / 4); e += 256) {
        int row = e >> 4, c4 = (e & 15) << 2;
        *(float4*)&Ks[row * KPAD + c4] = *(const float4*)&kb[row * HD + c4];
        *(float4*)&Vs[row * HD + c4]   = *(const float4*)&vb[row * HD + c4];
    }
    __syncthreads();

    const int w = tid >> 5, lane = tid & 31;
    float* Pw = Ps + w * 200 * PSTR;
    float* Qw = Qs + w * QBLK * HD;

    for (int qgi = w; qgi < NQG; qgi += 8) {
        const int q0 = qgi * QBLK;
        // stage 4 queries
#pragma unroll
        for (int qq = 0; qq < QBLK; qq++) {
            int q = q0 + qq;
            float2 qv = (q < NTOK) ? *(const float2*)&qg[(size_t)q * HD + lane * 2]
                                   : make_float2(0.f, 0.f);
            *(float2*)&Qw[qq * HD + lane * 2] = qv;
        }
        __syncwarp();

        float s[QBLK][7];
#pragma unroll
        for (int i = 0; i < 7; i++) {
            int m = lane + i * 32;
            if (m < NTOK) {
                float a[QBLK] = {0.f, 0.f, 0.f, 0.f};
#pragma unroll
                for (int d4 = 0; d4 < 16; d4++) {
                    float4 kk = *(const float4*)&Ks[m * KPAD + d4 * 4];
#pragma unroll
                    for (int qq = 0; qq < QBLK; qq++) {
                        float4 qf = *(const float4*)&Qw[qq * HD + d4 * 4];
                        a[qq] = fmaf(kk.x, qf.x, a[qq]);
                        a[qq] = fmaf(kk.y, qf.y, a[qq]);
                        a[qq] = fmaf(kk.z, qf.z, a[qq]);
                        a[qq] = fmaf(kk.w, qf.w, a[qq]);
                    }
                }
#pragma unroll
                for (int qq = 0; qq < QBLK; qq++) {
                    int q = q0 + qq;
                    s[qq][i] = a[qq] + ((q < NTOK) ? rb[(size_t)q * NTOK + m] : 0.f);
                }
            } else {
#pragma unroll
                for (int qq = 0; qq < QBLK; qq++) s[qq][i] = -1e30f;
            }
        }
        // softmax per query, write P transposed [m][qq]
#pragma unroll
        for (int qq = 0; qq < QBLK; qq++) {
            float mx = s[qq][0];
#pragma unroll
            for (int i = 1; i < 7; i++) mx = fmaxf(mx, s[qq][i]);
#pragma unroll
            for (int o = 16; o > 0; o >>= 1) mx = fmaxf(mx, __shfl_xor_sync(0xffffffffu, mx, o));
            float sum = 0.f;
#pragma unroll
            for (int i = 0; i < 7; i++) {
                int m = lane + i * 32;
                s[qq][i] = (m < NTOK) ? __expf(s[qq][i] - mx) : 0.f;
                sum += s[qq][i];
            }
#pragma unroll
            for (int o = 16; o > 0; o >>= 1) sum += __shfl_xor_sync(0xffffffffu, sum, o);
            float inv = 1.f / sum;
#pragma unroll
            for (int i = 0; i < 7; i++) {
                int m = lane + i * 32;
                if (m < NTOK) Pw[m * PSTR + qq] = s[qq][i] * inv;
            }
        }
        __syncwarp();

        // PV: o[qq][d], d = lane*2, lane*2+1
        float2 o2[QBLK] = {{0.f,0.f},{0.f,0.f},{0.f,0.f},{0.f,0.f}};
        for (int m = 0; m < NTOK; m++) {
            float2 vv = *(const float2*)&Vs[m * HD + lane * 2];
            float p0 = Pw[m * PSTR + 0];
            float p1 = Pw[m * PSTR + 1];
            float p2 = Pw[m * PSTR + 2];
            float p3 = Pw[m * PSTR + 3];
            o2[0].x = fmaf(p0, vv.x, o2[0].x); o2[0].y = fmaf(p0, vv.y, o2[0].y);
            o2[1].x = fmaf(p1, vv.x, o2[1].x); o2[1].y = fmaf(p1, vv.y, o2[1].y);
            o2[2].x = fmaf(p2, vv.x, o2[2].x); o2[2].y = fmaf(p2, vv.y, o2[2].y);
            o2[3].x = fmaf(p3, vv.x, o2[3].x); o2[3].y = fmaf(p3, vv.y, o2[3].y);
        }
        // write split-bf16 attention output directly
#pragma unroll
        for (int qq = 0; qq < QBLK; qq++) {
            int q = q0 + qq;
            if (q < NTOK) {
                size_t base = ((size_t)(b * NTOK + q)) * CDIM + h * HD + lane * 2;
                __nv_bfloat16 b0,s0,b1,s1;
                split1(o2[qq].x, b0, s0);
                split1(o2[qq].y, b1, s1);
                *(__nv_bfloat162*)&g_aob[base] = {b0, b1};
                *(__nv_bfloat162*)&g_aos[base] = {s0, s1};
            }
        }
        __syncwarp();
    }
}

// ======================= launch =======================
extern "C" void kernel_launch(void* const* d_in, const int* in_sizes, int n_in,
                              void* d_out, int out_size) {
    const float* x        = (const float*)d_in[0];
    const float* qkv_w    = (const float*)d_in[1];
    const float* q_bias   = (const float*)d_in[2];
    const float* v_bias   = (const float*)d_in[3];
    const float* rel_tab  = (const float*)d_in[4];
    const float* proj_w   = (const float*)d_in[5];
    const float* proj_b   = (const float*)d_in[6];
    const int*   rel_idx  = (const int*)d_in[7];
    float* out = (float*)d_out;

    cudaFuncSetAttribute(qkv_gemm_kernel,  cudaFuncAttributeMaxDynamicSharedMemorySize, SMEM_GEMM);
    cudaFuncSetAttribute(proj_gemm_kernel, cudaFuncAttributeMaxDynamicSharedMemorySize, SMEM_GEMM);
    cudaFuncSetAttribute(attn_kernel,      cudaFuncAttributeMaxDynamicSharedMemorySize, SMEM_ATTN);

    relbias_kernel<<<(NTOK * NTOK + 255) / 256, 256>>>(rel_tab, rel_idx);

    // split inputs/weights into bf16 pairs (device symbols resolved on device)
    {
        __nv_bfloat16 *xb, *xs, *wqb, *wqs, *wpb, *wps;
        cudaGetSymbolAddress((void**)&xb,  g_xb);
        cudaGetSymbolAddress((void**)&xs,  g_xs);
        cudaGetSymbolAddress((void**)&wqb, g_wqb);
        cudaGetSymbolAddress((void**)&wqs, g_wqs);
        cudaGetSymbolAddress((void**)&wpb, g_wpb);
        cudaGetSymbolAddress((void**)&wps, g_wps);
        int n4x = MROWS * KDIM / 4;
        split_kernel<<<(n4x + 255) / 256, 256>>>(x, xb, xs, n4x);
        int n4q = N_QKV * KDIM / 4;
        split_kernel<<<(n4q + 255) / 256, 256>>>(qkv_w, wqb, wqs, n4q);
        int n4p = CDIM * CDIM / 4;
        split_kernel<<<(n4p + 255) / 256, 256>>>(proj_w, wpb, wps, n4p);
    }

    {
        dim3 grid(N_QKV / GBN, MROWS / GBM);  // (36, 197)
        qkv_gemm_kernel<<<grid, 256, SMEM_GEMM>>>(q_bias, v_bias);
    }

    attn_kernel<<<BATCH * HEADS, 256, SMEM_ATTN>>>();

    {
        dim3 grid(CDIM / GBN, MROWS / GBM);   // (12, 197)
        proj_gemm_kernel<<<grid, 256, SMEM_GEMM>>>(proj_b, out);
    }
}

// round 7
// speedup vs baseline: 1.9630x; 1.3119x over previous
#include <cuda_runtime.h>
#include <cuda_bf16.h>
#include <cstdint>

// Problem constants
#define BATCH 128
#define HEADS 12
#define NTOK  197
#define CDIM  768
#define HD    64
#define MROWS (BATCH * NTOK) // 25216
#define KDIM  768
#define N_QKV (3 * CDIM)     // 2304

// -------- fp32 scratch --------
__device__ float g_q [BATCH * HEADS * NTOK * HD];
__device__ float g_k [BATCH * HEADS * NTOK * HD];
__device__ float g_v [BATCH * HEADS * NTOK * HD];
__device__ float g_rb[HEADS * NTOK * NTOK];

// -------- bf16 split scratch (big/small pairs) --------
__device__ __nv_bfloat16 g_xb [MROWS * KDIM];
__device__ __nv_bfloat16 g_xs [MROWS * KDIM];
__device__ __nv_bfloat16 g_wqb[N_QKV * KDIM];
__device__ __nv_bfloat16 g_wqs[N_QKV * KDIM];
__device__ __nv_bfloat16 g_wpb[CDIM * CDIM];
__device__ __nv_bfloat16 g_wps[CDIM * CDIM];
__device__ __nv_bfloat16 g_aob[MROWS * CDIM];
__device__ __nv_bfloat16 g_aos[MROWS * CDIM];

// ======================= rel-pos bias gather =======================
__global__ void relbias_kernel(const float* __restrict__ table,
                               const int* __restrict__ idx) {
    int i = blockIdx.x * 256 + threadIdx.x;
    if (i < NTOK * NTOK) {
        int id = idx[i];
#pragma unroll
        for (int h = 0; h < HEADS; h++)
            g_rb[h * NTOK * NTOK + i] = table[id * HEADS + h];
    }
}

// ======================= fp32 -> bf16{big,small} split =======================
__device__ __forceinline__ void split1(float v, __nv_bfloat16& b, __nv_bfloat16& s) {
    b = __float2bfloat16_rn(v);
    s = __float2bfloat16_rn(v - __bfloat162float(b));
}

__global__ void split_kernel(const float* __restrict__ src,
                             __nv_bfloat16* __restrict__ big,
                             __nv_bfloat16* __restrict__ small, int n4) {
    int i = blockIdx.x * 256 + threadIdx.x;
    if (i < n4) {
        float4 v = *(const float4*)&src[i * 4];
        __nv_bfloat16 b0,s0,b1,s1,b2,s2,b3,s3;
        split1(v.x,b0,s0); split1(v.y,b1,s1); split1(v.z,b2,s2); split1(v.w,b3,s3);
        *(__nv_bfloat162*)&big  [i*4    ] = {b0,b1};
        *(__nv_bfloat162*)&big  [i*4 + 2] = {b2,b3};
        *(__nv_bfloat162*)&small[i*4    ] = {s0,s1};
        *(__nv_bfloat162*)&small[i*4 + 2] = {s2,s3};
    }
}

// ======================= bf16 3-pass GEMM: ldmatrix + cp.async pipeline ==========
// C[m,n] = sum_k A[m,k]*B[n,k]. CTA 128x64, k-chunk 32, 8 warps (4M x 2N),
// warp tile 32x32. Double-buffered cp.async stages; XOR-swizzled 64B rows.
#define GBK 32
#define NKT (KDIM / GBK)     // 24
// per-stage smem offsets (bytes)
#define OFF_AB 0
#define OFF_AS 8192
#define OFF_BB 16384
#define OFF_BS 20480
#define STG    24576
#define SMEM_GEMM (2 * STG)  // 49152

__device__ __forceinline__ uint32_t smem_u32(const void* p) {
    uint32_t a;
    asm("{ .reg .u64 t; cvta.to.shared.u64 t, %1; cvt.u32.u64 %0, t; }" : "=r"(a) : "l"(p));
    return a;
}
__device__ __forceinline__ void cp16(uint32_t d, const void* s) {
    asm volatile("cp.async.cg.shared.global [%0], [%1], 16;" :: "r"(d), "l"(s));
}
__device__ __forceinline__ void ldsm4(unsigned& a0, unsigned& a1, unsigned& a2, unsigned& a3,
                                      uint32_t addr) {
    asm volatile("ldmatrix.sync.aligned.m8n8.x4.shared.b16 {%0,%1,%2,%3}, [%4];"
        : "=r"(a0), "=r"(a1), "=r"(a2), "=r"(a3) : "r"(addr));
}
__device__ __forceinline__ void mma16(float* c, const unsigned* a, const unsigned* b) {
    asm volatile("mma.sync.aligned.m16n8k16.row.col.f32.bf16.bf16.f32 "
        "{%0,%1,%2,%3}, {%4,%5,%6,%7}, {%8,%9}, {%0,%1,%2,%3};"
        : "+f"(c[0]), "+f"(c[1]), "+f"(c[2]), "+f"(c[3])
        : "r"(a[0]), "r"(a[1]), "r"(a[2]), "r"(a[3]), "r"(b[0]), "r"(b[1]));
}

// swizzled byte offset within a 64B-row buffer: rows r, 16B chunk c (0..3)
__device__ __forceinline__ uint32_t sw_off(int r, int c) {
    return (uint32_t)(r * 64 + ((c ^ ((r >> 1) & 3)) << 4));
}

// issue cp.async for one k-chunk into stage buffer
__device__ __forceinline__ void load_stage(
    uint32_t sb,
    const __nv_bfloat16* __restrict__ Ab, const __nv_bfloat16* __restrict__ As,
    const __nv_bfloat16* __restrict__ Bb, const __nv_bfloat16* __restrict__ Bs,
    int m0, int n0, int kt, int tid) {
#pragma unroll
    for (int i = 0; i < 2; i++) {          // A: 128 rows x 4 chunks = 512
        int id = i * 256 + tid;
        int r = id >> 2, c = id & 3;
        size_t src = (size_t)(m0 + r) * KDIM + kt + c * 8;
        uint32_t d = sw_off(r, c);
        cp16(sb + OFF_AB + d, Ab + src);
        cp16(sb + OFF_AS + d, As + src);
    }
    {                                       // B: 64 rows x 4 chunks = 256
        int r = tid >> 2, c = tid & 3;
        size_t src = (size_t)(n0 + r) * KDIM + kt + c * 8;
        uint32_t d = sw_off(r, c);
        cp16(sb + OFF_BB + d, Bb + src);
        cp16(sb + OFF_BS + d, Bs + src);
    }
    asm volatile("cp.async.commit_group;" ::: "memory");
}

__device__ __forceinline__ void gemm_mainloop(
    const __nv_bfloat16* __restrict__ Ab, const __nv_bfloat16* __restrict__ As,
    const __nv_bfloat16* __restrict__ Bb, const __nv_bfloat16* __restrict__ Bs,
    int m0, int n0, uint32_t smem_base, float acc[2][4][4]) {

    const int tid = threadIdx.x;
    const int lane = tid & 31, warp = tid >> 5;
    const int mbase = (warp & 3) * 32;
    const int nbase = (warp >> 2) * 32;

#pragma unroll
    for (int a = 0; a < 2; a++)
#pragma unroll
        for (int b = 0; b < 4; b++)
#pragma unroll
            for (int c = 0; c < 4; c++) acc[a][b][c] = 0.f;

    // per-lane ldmatrix row/chunk components
    const int a_row = mbase + (lane & 15);          // + mt*16
    const int a_hi  = lane >> 4;                    // k 16B half
    const int b_row = nbase + (lane & 7) + ((lane >> 4) & 1) * 8;  // + bt*16
    const int b_hi  = (lane >> 3) & 1;

    load_stage(smem_base, Ab, As, Bb, Bs, m0, n0, 0, tid);

    for (int t = 0; t < NKT; t++) {
        uint32_t sb = smem_base + (t & 1) * STG;
        if (t + 1 < NKT)
            load_stage(smem_base + ((t + 1) & 1) * STG, Ab, As, Bb, Bs,
                       m0, n0, (t + 1) * GBK, tid);
        if (t + 1 < NKT) asm volatile("cp.async.wait_group 1;" ::: "memory");
        else             asm volatile("cp.async.wait_group 0;" ::: "memory");
        __syncthreads();

#pragma unroll
        for (int kk = 0; kk < 2; kk++) {
            unsigned Afb[2][4], Afs[2][4], Bfb[4][2], Bfs[4][2];
#pragma unroll
            for (int mt = 0; mt < 2; mt++) {
                int r = a_row + mt * 16;
                uint32_t off = sw_off(r, kk * 2 + a_hi);
                ldsm4(Afb[mt][0], Afb[mt][1], Afb[mt][2], Afb[mt][3], sb + OFF_AB + off);
                ldsm4(Afs[mt][0], Afs[mt][1], Afs[mt][2], Afs[mt][3], sb + OFF_AS + off);
            }
#pragma unroll
            for (int bt = 0; bt < 2; bt++) {
                int r = b_row + bt * 16;
                uint32_t off = sw_off(r, kk * 2 + b_hi);
                ldsm4(Bfb[bt*2][0], Bfb[bt*2][1], Bfb[bt*2+1][0], Bfb[bt*2+1][1],
                      sb + OFF_BB + off);
                ldsm4(Bfs[bt*2][0], Bfs[bt*2][1], Bfs[bt*2+1][0], Bfs[bt*2+1][1],
                      sb + OFF_BS + off);
            }
#pragma unroll
            for (int mt = 0; mt < 2; mt++)
#pragma unroll
                for (int nt = 0; nt < 4; nt++) {
                    mma16(acc[mt][nt], Afb[mt], Bfb[nt]);  // big*big
                    mma16(acc[mt][nt], Afb[mt], Bfs[nt]);  // big*small
                    mma16(acc[mt][nt], Afs[mt], Bfb[nt]);  // small*big
                }
        }
        __syncthreads();
    }
}

// ---- QKV GEMM: bx in 0..35; which = bx/12, h = bx%12; scatter epilogue ----
__global__ __launch_bounds__(256, 2)
void qkv_gemm_kernel(const float* __restrict__ q_bias, const float* __restrict__ v_bias) {
    extern __shared__ char smg[];
    const int bx = blockIdx.x, m0 = blockIdx.y * 128;
    float acc[2][4][4];
    gemm_mainloop(g_xb, g_xs, g_wqb, g_wqs, m0, bx * 64, smem_u32(smg), acc);

    const int lane = threadIdx.x & 31, warp = threadIdx.x >> 5;
    const int tig = lane & 3, gid = lane >> 2;
    const int mbase = (warp & 3) * 32, nbase = (warp >> 2) * 32;
    const int which = bx / HEADS, h = bx % HEADS;
    const float scale = 0.125f;

#pragma unroll
    for (int mt = 0; mt < 2; mt++)
#pragma unroll
        for (int nt = 0; nt < 4; nt++) {
            int d = nbase + nt * 8 + tig * 2;
#pragma unroll
            for (int half = 0; half < 2; half++) {
                int m = m0 + mbase + mt * 16 + gid + half * 8;
                int b_i = m / NTOK, tok = m % NTOK;
                size_t base = ((size_t)(b_i * HEADS + h) * NTOK + tok) * HD + d;
                float2 o = make_float2(acc[mt][nt][half * 2 + 0], acc[mt][nt][half * 2 + 1]);
                if (which == 0) {
                    float2 qb = *(const float2*)&q_bias[h * HD + d];
                    o.x = (o.x + qb.x) * scale;
                    o.y = (o.y + qb.y) * scale;
                    *(float2*)&g_q[base] = o;
                } else if (which == 1) {
                    *(float2*)&g_k[base] = o;
                } else {
                    float2 vb = *(const float2*)&v_bias[h * HD + d];
                    o.x += vb.x; o.y += vb.y;
                    *(float2*)&g_v[base] = o;
                }
            }
        }
}

// ---- output projection GEMM ----
__global__ __launch_bounds__(256, 2)
void proj_gemm_kernel(const float* __restrict__ bias, float* __restrict__ out) {
    extern __shared__ char smg[];
    const int bx = blockIdx.x, m0 = blockIdx.y * 128;
    float acc[2][4][4];
    gemm_mainloop(g_aob, g_aos, g_wpb, g_wps, m0, bx * 64, smem_u32(smg), acc);

    const int lane = threadIdx.x & 31, warp = threadIdx.x >> 5;
    const int tig = lane & 3, gid = lane >> 2;
    const int mbase = (warp & 3) * 32, nbase = (warp >> 2) * 32;

#pragma unroll
    for (int mt = 0; mt < 2; mt++)
#pragma unroll
        for (int nt = 0; nt < 4; nt++) {
            int ng = bx * 64 + nbase + nt * 8 + tig * 2;
            float2 bb = *(const float2*)&bias[ng];
#pragma unroll
            for (int half = 0; half < 2; half++) {
                int m = m0 + mbase + mt * 16 + gid + half * 8;
                float2 o = make_float2(acc[mt][nt][half * 2 + 0] + bb.x,
                                       acc[mt][nt][half * 2 + 1] + bb.y);
                *(float2*)&out[(size_t)m * CDIM + ng] = o;
            }
        }
}

// ======================= attention (q-blocked SIMT, unchanged) =======================
#define QBLK 4
#define NQG  ((NTOK + QBLK - 1) / QBLK)  // 50
#define KPAD 68
#define PSTR 5
#define SM_K (NTOK * KPAD)
#define SM_V (NTOK * HD)
#define SM_P (8 * 200 * PSTR)
#define SM_Q (8 * QBLK * HD)
#define SMEM_ATTN ((SM_K + SM_V + SM_P + SM_Q) * 4)  // 144208 B

__global__ __launch_bounds__(256)
void attn_kernel() {
    extern __shared__ float sma[];
    float* Ks = sma;
    float* Vs = Ks + SM_K;
    float* Ps = Vs + SM_V;
    float* Qs = Ps + SM_P;

    const int bh = blockIdx.x;
    const int b = bh / HEADS, h = bh % HEADS;
    const int tid = threadIdx.x;
    const float* kb = g_k + (size_t)bh * NTOK * HD;
    const float* vb = g_v + (size_t)bh * NTOK * HD;
    const float* qg = g_q + (size_t)bh * NTOK * HD;
    const float* rb = g_rb + (size_t)h * NTOK * NTOK;

    for (int e = tid; e < NTOK * (HD / 4); e += 256) {
        int row = e >> 4, c4 = (e & 15) << 2;
        *(float4*)&Ks[row * KPAD + c4] = *(const float4*)&kb[row * HD + c4];
        *(float4*)&Vs[row * HD + c4]   = *(const float4*)&vb[row * HD + c4];
    }
    __syncthreads();

    const int w = tid >> 5, lane = tid & 31;
    float* Pw = Ps + w * 200 * PSTR;
    float* Qw = Qs + w * QBLK * HD;

    for (int qgi = w; qgi < NQG; qgi += 8) {
        const int q0 = qgi * QBLK;
#pragma unroll
        for (int qq = 0; qq < QBLK; qq++) {
            int q = q0 + qq;
            float2 qv = (q < NTOK) ? *(const float2*)&qg[(size_t)q * HD + lane * 2]
                                   : make_float2(0.f, 0.f);
            *(float2*)&Qw[qq * HD + lane * 2] = qv;
        }
        __syncwarp();

        float s[QBLK][7];
#pragma unroll
        for (int i = 0; i < 7; i++) {
            int m = lane + i * 32;
            if (m < NTOK) {
                float a[QBLK] = {0.f, 0.f, 0.f, 0.f};
#pragma unroll
                for (int d4 = 0; d4 < 16; d4++) {
                    float4 kk = *(const float4*)&Ks[m * KPAD + d4 * 4];
#pragma unroll
                    for (int qq = 0; qq < QBLK; qq++) {
                        float4 qf = *(const float4*)&Qw[qq * HD + d4 * 4];
                        a[qq] = fmaf(kk.x, qf.x, a[qq]);
                        a[qq] = fmaf(kk.y, qf.y, a[qq]);
                        a[qq] = fmaf(kk.z, qf.z, a[qq]);
                        a[qq] = fmaf(kk.w, qf.w, a[qq]);
                    }
                }
#pragma unroll
                for (int qq = 0; qq < QBLK; qq++) {
                    int q = q0 + qq;
                    s[qq][i] = a[qq] + ((q < NTOK) ? rb[(size_t)q * NTOK + m] : 0.f);
                }
            } else {
#pragma unroll
                for (int qq = 0; qq < QBLK; qq++) s[qq][i] = -1e30f;
            }
        }
#pragma unroll
        for (int qq = 0; qq < QBLK; qq++) {
            float mx = s[qq][0];
#pragma unroll
            for (int i = 1; i < 7; i++) mx = fmaxf(mx, s[qq][i]);
#pragma unroll
            for (int o = 16; o > 0; o >>= 1) mx = fmaxf(mx, __shfl_xor_sync(0xffffffffu, mx, o));
            float sum = 0.f;
#pragma unroll
            for (int i = 0; i < 7; i++) {
                int m = lane + i * 32;
                s[qq][i] = (m < NTOK) ? __expf(s[qq][i] - mx) : 0.f;
                sum += s[qq][i];
            }
#pragma unroll
            for (int o = 16; o > 0; o >>= 1) sum += __shfl_xor_sync(0xffffffffu, sum, o);
            float inv = 1.f / sum;
#pragma unroll
            for (int i = 0; i < 7; i++) {
                int m = lane + i * 32;
                if (m < NTOK) Pw[m * PSTR + qq] = s[qq][i] * inv;
            }
        }
        __syncwarp();

        float2 o2[QBLK] = {{0.f,0.f},{0.f,0.f},{0.f,0.f},{0.f,0.f}};
        for (int m = 0; m < NTOK; m++) {
            float2 vv = *(const float2*)&Vs[m * HD + lane * 2];
            float p0 = Pw[m * PSTR + 0];
            float p1 = Pw[m * PSTR + 1];
            float p2 = Pw[m * PSTR + 2];
            float p3 = Pw[m * PSTR + 3];
            o2[0].x = fmaf(p0, vv.x, o2[0].x); o2[0].y = fmaf(p0, vv.y, o2[0].y);
            o2[1].x = fmaf(p1, vv.x, o2[1].x); o2[1].y = fmaf(p1, vv.y, o2[1].y);
            o2[2].x = fmaf(p2, vv.x, o2[2].x); o2[2].y = fmaf(p2, vv.y, o2[2].y);
            o2[3].x = fmaf(p3, vv.x, o2[3].x); o2[3].y = fmaf(p3, vv.y, o2[3].y);
        }
#pragma unroll
        for (int qq = 0; qq < QBLK; qq++) {
            int q = q0 + qq;
            if (q < NTOK) {
                size_t base = ((size_t)(b * NTOK + q)) * CDIM + h * HD + lane * 2;
                __nv_bfloat16 b0,s0,b1,s1;
                split1(o2[qq].x, b0, s0);
                split1(o2[qq].y, b1, s1);
                *(__nv_bfloat162*)&g_aob[base] = {b0, b1};
                *(__nv_bfloat162*)&g_aos[base] = {s0, s1};
            }
        }
        __syncwarp();
    }
}

// ======================= launch =======================
extern "C" void kernel_launch(void* const* d_in, const int* in_sizes, int n_in,
                              void* d_out, int out_size) {
    const float* x        = (const float*)d_in[0];
    const float* qkv_w    = (const float*)d_in[1];
    const float* q_bias   = (const float*)d_in[2];
    const float* v_bias   = (const float*)d_in[3];
    const float* rel_tab  = (const float*)d_in[4];
    const float* proj_w   = (const float*)d_in[5];
    const float* proj_b   = (const float*)d_in[6];
    const int*   rel_idx  = (const int*)d_in[7];
    float* out = (float*)d_out;

    static_assert(MROWS % 128 == 0 && N_QKV % 64 == 0 && CDIM % 64 == 0, "tiling");

    cudaFuncSetAttribute(qkv_gemm_kernel,  cudaFuncAttributeMaxDynamicSharedMemorySize, SMEM_GEMM);
    cudaFuncSetAttribute(proj_gemm_kernel, cudaFuncAttributeMaxDynamicSharedMemorySize, SMEM_GEMM);
    cudaFuncSetAttribute(attn_kernel,      cudaFuncAttributeMaxDynamicSharedMemorySize, SMEM_ATTN);

    relbias_kernel<<<(NTOK * NTOK + 255) / 256, 256>>>(rel_tab, rel_idx);

    {
        __nv_bfloat16 *xb, *xs, *wqb, *wqs, *wpb, *wps;
        cudaGetSymbolAddress((void**)&xb,  g_xb);
        cudaGetSymbolAddress((void**)&xs,  g_xs);
        cudaGetSymbolAddress((void**)&wqb, g_wqb);
        cudaGetSymbolAddress((void**)&wqs, g_wqs);
        cudaGetSymbolAddress((void**)&wpb, g_wpb);
        cudaGetSymbolAddress((void**)&wps, g_wps);
        int n4x = MROWS * KDIM / 4;
        split_kernel<<<(n4x + 255) / 256, 256>>>(x, xb, xs, n4x);
        int n4q = N_QKV * KDIM / 4;
        split_kernel<<<(n4q + 255) / 256, 256>>>(qkv_w, wqb, wqs, n4q);
        int n4p = CDIM * CDIM / 4;
        split_kernel<<<(n4p + 255) / 256, 256>>>(proj_w, wpb, wps, n4p);
    }

    {
        dim3 grid(N_QKV / 64, MROWS / 128);  // (36, 197)
        qkv_gemm_kernel<<<grid, 256, SMEM_GEMM>>>(q_bias, v_bias);
    }

    attn_kernel<<<BATCH * HEADS, 256, SMEM_ATTN>>>();

    {
        dim3 grid(CDIM / 64, MROWS / 128);   // (12, 197)
        proj_gemm_kernel<<<grid, 256, SMEM_GEMM>>>(proj_b, out);
    }
}